// round 4
// baseline (speedup 1.0000x reference)
#include <cuda_runtime.h>
#include <cuda_bf16.h>
#include <math.h>

#define N_NODES 100000
#define N_EDGES 1600000
#define NFEAT 64
#define NHID 64
#define NCLASS 40
#define SCAN_B 1024
#define SCAN_NB ((N_NODES + SCAN_B - 1) / SCAN_B)   // 98

// ---------------- device scratch (no allocations allowed) ----------------
__device__ int2  g_edges[N_EDGES];            // (src, dst) as int32
__device__ int   g_deg[N_NODES];
__device__ int   g_start[N_NODES + 1];        // CSR row offsets (by dst)
__device__ int   g_cursor[N_NODES];
__device__ int   g_bsum[128];
__device__ int   g_csr_src[N_EDGES];          // srcs grouped by dst
__device__ float g_h[N_NODES * NHID];         // layer-1 output
__device__ int   g_is64;                      // edge_index dtype flag

// ---------------- dtype sniff: int64 vs int32 edge_index ----------------
__global__ void sniff_kernel(const unsigned int* __restrict__ w) {
    __shared__ int any;
    if (threadIdx.x == 0) any = 0;
    __syncthreads();
    unsigned int v = w[threadIdx.x * 2 + 1];
    if (v != 0u) atomicOr(&any, 1);
    __syncthreads();
    if (threadIdx.x == 0) g_is64 = (any == 0) ? 1 : 0;
}

__global__ void zero_deg_kernel() {
    int i = blockIdx.x * blockDim.x + threadIdx.x;
    if (i < N_NODES) g_deg[i] = 0;
}

// fused: int64/int32 -> int2 conversion + degree histogram
__global__ void convert_hist_kernel(const void* __restrict__ ei) {
    int e = blockIdx.x * blockDim.x + threadIdx.x;
    if (e >= N_EDGES) return;
    int s, d;
    if (g_is64) {
        const long long* p = (const long long*)ei;
        s = (int)p[e];
        d = (int)p[N_EDGES + e];
    } else {
        const int* p = (const int*)ei;
        s = p[e];
        d = p[N_EDGES + e];
    }
    g_edges[e] = make_int2(s, d);
    atomicAdd(&g_deg[d], 1);
}

// pass 1: per-block exclusive scan (Hillis-Steele), block sums to g_bsum
__global__ __launch_bounds__(SCAN_B) void scan1_kernel() {
    __shared__ int sm[SCAN_B];
    int i = blockIdx.x * SCAN_B + threadIdx.x;
    int v = (i < N_NODES) ? g_deg[i] : 0;
    sm[threadIdx.x] = v;
    __syncthreads();
    #pragma unroll
    for (int o = 1; o < SCAN_B; o <<= 1) {
        int a = (threadIdx.x >= o) ? sm[threadIdx.x - o] : 0;
        __syncthreads();
        sm[threadIdx.x] += a;
        __syncthreads();
    }
    if (i < N_NODES) g_start[i] = sm[threadIdx.x] - v;
    if (threadIdx.x == SCAN_B - 1) g_bsum[blockIdx.x] = sm[SCAN_B - 1];
}

__global__ void scan2_kernel() {
    __shared__ int sm[128];
    int v = (threadIdx.x < SCAN_NB) ? g_bsum[threadIdx.x] : 0;
    sm[threadIdx.x] = v;
    __syncthreads();
    #pragma unroll
    for (int o = 1; o < 128; o <<= 1) {
        int a = (threadIdx.x >= o) ? sm[threadIdx.x - o] : 0;
        __syncthreads();
        sm[threadIdx.x] += a;
        __syncthreads();
    }
    if (threadIdx.x < SCAN_NB) g_bsum[threadIdx.x] = sm[threadIdx.x] - v;
}

__global__ void scan3_kernel() {
    int i = blockIdx.x * blockDim.x + threadIdx.x;
    if (i < N_NODES) {
        int s = g_start[i] + g_bsum[i >> 10];
        g_start[i] = s;
        g_cursor[i] = s;
    }
    if (i == 0) g_start[N_NODES] = N_EDGES;
}

__global__ void fill_kernel() {
    int e = blockIdx.x * blockDim.x + threadIdx.x;
    if (e >= N_EDGES) return;
    int2 ed = g_edges[e];
    int pos = atomicAdd(&g_cursor[ed.y], 1);
    g_csr_src[pos] = ed.x;
}

// ---------------- gather device helper ----------------
// Warp covers 2 rows (lanes 0-15 row A, 16-31 row B); each lane owns one
// float4 column chunk. Per neighbor: one contiguous 256B row read.
__device__ __forceinline__ float4 gather_row(const float4* __restrict__ X4,
                                             int row, int q, int n) {
    float4 acc = make_float4(0.f, 0.f, 0.f, 0.f);
    if (row >= n) return acc;
    acc = X4[(long long)row * 16 + q];
    int j = g_start[row], end = g_start[row + 1];
    for (; j + 3 < end; j += 4) {
        int s0 = g_csr_src[j], s1 = g_csr_src[j + 1];
        int s2 = g_csr_src[j + 2], s3 = g_csr_src[j + 3];
        float4 v0 = X4[(long long)s0 * 16 + q];
        float4 v1 = X4[(long long)s1 * 16 + q];
        float4 v2 = X4[(long long)s2 * 16 + q];
        float4 v3 = X4[(long long)s3 * 16 + q];
        acc.x += v0.x + v1.x + v2.x + v3.x;
        acc.y += v0.y + v1.y + v2.y + v3.y;
        acc.z += v0.z + v1.z + v2.z + v3.z;
        acc.w += v0.w + v1.w + v2.w + v3.w;
    }
    for (; j < end; j++) {
        float4 v = X4[(long long)g_csr_src[j] * 16 + q];
        acc.x += v.x; acc.y += v.y; acc.z += v.z; acc.w += v.w;
    }
    return acc;
}

// ---------------- layer 1: gather + (X+AGG)@W1 + b1 + ReLU -> g_h ----------------
__global__ __launch_bounds__(256) void gin_layer1_kernel(
    const float* __restrict__ X, const float* __restrict__ W,
    const float* __restrict__ B, float* __restrict__ OUT, int n)
{
    __shared__ float As[64][65];
    __shared__ __align__(16) float Ws[64][64];
    __shared__ float Bs[64];

    int t = threadIdx.x;
    int row0 = blockIdx.x * 64;
    int lane = t & 31, warp = t >> 5;

    #pragma unroll
    for (int i = 0; i < 4; i++)
        ((float4*)Ws)[t + i * 256] = ((const float4*)W)[t + i * 256];
    if (t < 64) Bs[t] = B[t];

    // gather: warp handles row pairs (rr, rr+1), 4 passes
    int half = lane >> 4;      // 0 or 1
    int q = lane & 15;         // float4 chunk
    const float4* X4 = (const float4*)X;
    #pragma unroll
    for (int pass = 0; pass < 4; pass++) {
        int r = warp * 2 + pass * 16 + half;
        float4 acc = gather_row(X4, row0 + r, q, n);
        As[r][q * 4 + 0] = acc.x;
        As[r][q * 4 + 1] = acc.y;
        As[r][q * 4 + 2] = acc.z;
        As[r][q * 4 + 3] = acc.w;
    }
    __syncthreads();

    // GEMM: 4x4 per thread
    int tx = t & 15, ty = t >> 4;
    float c[4][4];
    #pragma unroll
    for (int i = 0; i < 4; i++)
        #pragma unroll
        for (int jj = 0; jj < 4; jj++)
            c[i][jj] = Bs[tx * 4 + jj];

    #pragma unroll
    for (int k = 0; k < 64; k++) {
        float4 b = *(const float4*)&Ws[k][tx * 4];
        float a0 = As[ty * 4 + 0][k];
        float a1 = As[ty * 4 + 1][k];
        float a2 = As[ty * 4 + 2][k];
        float a3 = As[ty * 4 + 3][k];
        c[0][0] += a0 * b.x; c[0][1] += a0 * b.y; c[0][2] += a0 * b.z; c[0][3] += a0 * b.w;
        c[1][0] += a1 * b.x; c[1][1] += a1 * b.y; c[1][2] += a1 * b.z; c[1][3] += a1 * b.w;
        c[2][0] += a2 * b.x; c[2][1] += a2 * b.y; c[2][2] += a2 * b.z; c[2][3] += a2 * b.w;
        c[3][0] += a3 * b.x; c[3][1] += a3 * b.y; c[3][2] += a3 * b.z; c[3][3] += a3 * b.w;
    }

    #pragma unroll
    for (int i = 0; i < 4; i++) {
        int orow = row0 + ty * 4 + i;
        if (orow < n) {
            float4 o;
            o.x = fmaxf(c[i][0], 0.f);
            o.y = fmaxf(c[i][1], 0.f);
            o.z = fmaxf(c[i][2], 0.f);
            o.w = fmaxf(c[i][3], 0.f);
            ((float4*)OUT)[(long long)orow * 16 + tx] = o;
        }
    }
}

// ---------------- layer 2 + classifier + log_softmax, fully fused ----------------
// gather(h) -> (h+agg)@W2+b2,ReLU (h2 stays in smem) -> @Wf+bf -> log_softmax -> out
__global__ __launch_bounds__(256) void gin_layer2_final_kernel(
    const float* __restrict__ H, const float* __restrict__ W,
    const float* __restrict__ B, const float* __restrict__ WF,
    const float* __restrict__ BF, float* __restrict__ OUT, int n)
{
    __shared__ float As[64][65];
    __shared__ __align__(16) float Ws[64][64];
    __shared__ float Bs[64];
    __shared__ float Wf_s[64][40];
    __shared__ float Bf_s[40];

    int t = threadIdx.x;
    int row0 = blockIdx.x * 64;
    int lane = t & 31, warp = t >> 5;

    #pragma unroll
    for (int i = 0; i < 4; i++)
        ((float4*)Ws)[t + i * 256] = ((const float4*)W)[t + i * 256];
    if (t < 64) Bs[t] = B[t];
    for (int idx = t; idx < 64 * 40; idx += 256)
        Wf_s[idx / 40][idx % 40] = WF[idx];
    if (t < 40) Bf_s[t] = BF[t];

    // gather
    int half = lane >> 4;
    int q = lane & 15;
    const float4* H4 = (const float4*)H;
    #pragma unroll
    for (int pass = 0; pass < 4; pass++) {
        int r = warp * 2 + pass * 16 + half;
        float4 acc = gather_row(H4, row0 + r, q, n);
        As[r][q * 4 + 0] = acc.x;
        As[r][q * 4 + 1] = acc.y;
        As[r][q * 4 + 2] = acc.z;
        As[r][q * 4 + 3] = acc.w;
    }
    __syncthreads();

    // GEMM 1: h2 = relu((h+agg)@W2 + b2), kept in registers
    int tx = t & 15, ty = t >> 4;
    float c[4][4];
    #pragma unroll
    for (int i = 0; i < 4; i++)
        #pragma unroll
        for (int jj = 0; jj < 4; jj++)
            c[i][jj] = Bs[tx * 4 + jj];

    #pragma unroll
    for (int k = 0; k < 64; k++) {
        float4 b = *(const float4*)&Ws[k][tx * 4];
        float a0 = As[ty * 4 + 0][k];
        float a1 = As[ty * 4 + 1][k];
        float a2 = As[ty * 4 + 2][k];
        float a3 = As[ty * 4 + 3][k];
        c[0][0] += a0 * b.x; c[0][1] += a0 * b.y; c[0][2] += a0 * b.z; c[0][3] += a0 * b.w;
        c[1][0] += a1 * b.x; c[1][1] += a1 * b.y; c[1][2] += a1 * b.z; c[1][3] += a1 * b.w;
        c[2][0] += a2 * b.x; c[2][1] += a2 * b.y; c[2][2] += a2 * b.z; c[2][3] += a2 * b.w;
        c[3][0] += a3 * b.x; c[3][1] += a3 * b.y; c[3][2] += a3 * b.z; c[3][3] += a3 * b.w;
    }
    __syncthreads();   // everyone done reading As

    // restage relu(h2) into As
    #pragma unroll
    for (int i = 0; i < 4; i++) {
        int r = ty * 4 + i;
        As[r][tx * 4 + 0] = fmaxf(c[i][0], 0.f);
        As[r][tx * 4 + 1] = fmaxf(c[i][1], 0.f);
        As[r][tx * 4 + 2] = fmaxf(c[i][2], 0.f);
        As[r][tx * 4 + 3] = fmaxf(c[i][3], 0.f);
    }
    __syncthreads();

    // GEMM 2 + log_softmax: 4 threads/row, 10 cols each
    int tx4 = t & 3, ty4 = t >> 2;
    float acc[10];
    #pragma unroll
    for (int j = 0; j < 10; j++) acc[j] = Bf_s[tx4 * 10 + j];

    #pragma unroll
    for (int k = 0; k < 64; k++) {
        float a = As[ty4][k];
        #pragma unroll
        for (int j = 0; j < 10; j++)
            acc[j] += a * Wf_s[k][tx4 * 10 + j];
    }

    float m = acc[0];
    #pragma unroll
    for (int j = 1; j < 10; j++) m = fmaxf(m, acc[j]);
    m = fmaxf(m, __shfl_xor_sync(0xFFFFFFFFu, m, 1));
    m = fmaxf(m, __shfl_xor_sync(0xFFFFFFFFu, m, 2));

    float s = 0.f;
    #pragma unroll
    for (int j = 0; j < 10; j++) s += __expf(acc[j] - m);
    s += __shfl_xor_sync(0xFFFFFFFFu, s, 1);
    s += __shfl_xor_sync(0xFFFFFFFFu, s, 2);

    float ls = m + __logf(s);

    int row = row0 + ty4;
    if (row < n) {
        #pragma unroll
        for (int j = 0; j < 10; j++)
            OUT[(long long)row * NCLASS + tx4 * 10 + j] = acc[j] - ls;
    }
}

// ---------------- launch ----------------
extern "C" void kernel_launch(void* const* d_in, const int* in_sizes, int n_in,
                              void* d_out, int out_size) {
    const float* x  = (const float*)d_in[0];
    const void*  ei = d_in[1];
    const float* W1 = (const float*)d_in[2];
    const float* b1 = (const float*)d_in[3];
    const float* W2 = (const float*)d_in[4];
    const float* b2 = (const float*)d_in[5];
    const float* Wf = (const float*)d_in[6];
    const float* bf = (const float*)d_in[7];
    float* out = (float*)d_out;

    float* h; cudaGetSymbolAddress((void**)&h, g_h);

    const int n = N_NODES;
    const int EB = (N_EDGES + 255) / 256;
    const int NB = (N_NODES + 255) / 256;
    const int GB = (n + 63) / 64;

    // edge preprocessing + CSR build
    sniff_kernel<<<1, 256>>>((const unsigned int*)ei);
    zero_deg_kernel<<<NB, 256>>>();
    convert_hist_kernel<<<EB, 256>>>(ei);
    scan1_kernel<<<SCAN_NB, SCAN_B>>>();
    scan2_kernel<<<1, 128>>>();
    scan3_kernel<<<NB, 256>>>();
    fill_kernel<<<EB, 256>>>();

    // layer 1
    gin_layer1_kernel<<<GB, 256>>>(x, W1, b1, h, n);
    // layer 2 + classifier + log_softmax
    gin_layer2_final_kernel<<<GB, 256>>>(h, W2, b2, Wf, bf, out, n);
}

// round 5
// speedup vs baseline: 1.0024x; 1.0024x over previous
#include <cuda_runtime.h>
#include <cuda_bf16.h>
#include <math.h>

#define N_NODES 100000
#define N_EDGES 1600000
#define NFEAT 64
#define NHID 64
#define NCLASS 40
#define SCAN_B 1024
#define SCAN_NB ((N_NODES + SCAN_B - 1) / SCAN_B)   // 98

// ---------------- device scratch (no allocations allowed) ----------------
__device__ int2  g_edges[N_EDGES];            // (src, dst) as int32
__device__ int   g_deg[N_NODES];
__device__ int   g_start[N_NODES + 1];        // CSR row offsets (by dst)
__device__ int   g_cursor[N_NODES];
__device__ int   g_bsum[128];
__device__ int   g_csr_src[N_EDGES];          // srcs grouped by dst
__device__ float g_h[N_NODES * NHID];         // layer-1 output
__device__ int   g_is64;                      // edge_index dtype flag

// ---------------- dtype sniff: int64 vs int32 edge_index ----------------
__global__ void sniff_kernel(const unsigned int* __restrict__ w) {
    __shared__ int any;
    if (threadIdx.x == 0) any = 0;
    __syncthreads();
    unsigned int v = w[threadIdx.x * 2 + 1];
    if (v != 0u) atomicOr(&any, 1);
    __syncthreads();
    if (threadIdx.x == 0) g_is64 = (any == 0) ? 1 : 0;
}

__global__ void zero_deg_kernel() {
    int i = blockIdx.x * blockDim.x + threadIdx.x;
    if (i < N_NODES) g_deg[i] = 0;
}

// fused: int64/int32 -> int2 conversion + degree histogram
__global__ void convert_hist_kernel(const void* __restrict__ ei) {
    int e = blockIdx.x * blockDim.x + threadIdx.x;
    if (e >= N_EDGES) return;
    int s, d;
    if (g_is64) {
        const long long* p = (const long long*)ei;
        s = (int)p[e];
        d = (int)p[N_EDGES + e];
    } else {
        const int* p = (const int*)ei;
        s = p[e];
        d = p[N_EDGES + e];
    }
    g_edges[e] = make_int2(s, d);
    atomicAdd(&g_deg[d], 1);
}

// pass 1: per-block exclusive scan (Hillis-Steele), block sums to g_bsum
__global__ __launch_bounds__(SCAN_B) void scan1_kernel() {
    __shared__ int sm[SCAN_B];
    int i = blockIdx.x * SCAN_B + threadIdx.x;
    int v = (i < N_NODES) ? g_deg[i] : 0;
    sm[threadIdx.x] = v;
    __syncthreads();
    #pragma unroll
    for (int o = 1; o < SCAN_B; o <<= 1) {
        int a = (threadIdx.x >= o) ? sm[threadIdx.x - o] : 0;
        __syncthreads();
        sm[threadIdx.x] += a;
        __syncthreads();
    }
    if (i < N_NODES) g_start[i] = sm[threadIdx.x] - v;
    if (threadIdx.x == SCAN_B - 1) g_bsum[blockIdx.x] = sm[SCAN_B - 1];
}

__global__ void scan2_kernel() {
    __shared__ int sm[128];
    int v = (threadIdx.x < SCAN_NB) ? g_bsum[threadIdx.x] : 0;
    sm[threadIdx.x] = v;
    __syncthreads();
    #pragma unroll
    for (int o = 1; o < 128; o <<= 1) {
        int a = (threadIdx.x >= o) ? sm[threadIdx.x - o] : 0;
        __syncthreads();
        sm[threadIdx.x] += a;
        __syncthreads();
    }
    if (threadIdx.x < SCAN_NB) g_bsum[threadIdx.x] = sm[threadIdx.x] - v;
}

__global__ void scan3_kernel() {
    int i = blockIdx.x * blockDim.x + threadIdx.x;
    if (i < N_NODES) {
        int s = g_start[i] + g_bsum[i >> 10];
        g_start[i] = s;
        g_cursor[i] = s;
    }
    if (i == 0) g_start[N_NODES] = N_EDGES;
}

__global__ void fill_kernel() {
    int e = blockIdx.x * blockDim.x + threadIdx.x;
    if (e >= N_EDGES) return;
    int2 ed = g_edges[e];
    int pos = atomicAdd(&g_cursor[ed.y], 1);
    g_csr_src[pos] = ed.x;
}

// ---------------- gather device helper ----------------
// Warp covers 2 rows (lanes 0-15 row A, 16-31 row B); each lane owns one
// float4 column chunk. Per neighbor: one contiguous 256B row read.
__device__ __forceinline__ float4 gather_row(const float4* __restrict__ X4,
                                             int row, int q, int n) {
    float4 acc = make_float4(0.f, 0.f, 0.f, 0.f);
    if (row >= n) return acc;
    acc = X4[(long long)row * 16 + q];
    int j = g_start[row], end = g_start[row + 1];
    for (; j + 3 < end; j += 4) {
        int s0 = g_csr_src[j], s1 = g_csr_src[j + 1];
        int s2 = g_csr_src[j + 2], s3 = g_csr_src[j + 3];
        float4 v0 = X4[(long long)s0 * 16 + q];
        float4 v1 = X4[(long long)s1 * 16 + q];
        float4 v2 = X4[(long long)s2 * 16 + q];
        float4 v3 = X4[(long long)s3 * 16 + q];
        acc.x += v0.x + v1.x + v2.x + v3.x;
        acc.y += v0.y + v1.y + v2.y + v3.y;
        acc.z += v0.z + v1.z + v2.z + v3.z;
        acc.w += v0.w + v1.w + v2.w + v3.w;
    }
    for (; j < end; j++) {
        float4 v = X4[(long long)g_csr_src[j] * 16 + q];
        acc.x += v.x; acc.y += v.y; acc.z += v.z; acc.w += v.w;
    }
    return acc;
}

// ---------------- layer 1: gather + (X+AGG)@W1 + b1 + ReLU -> g_h ----------------
__global__ __launch_bounds__(256) void gin_layer1_kernel(
    const float* __restrict__ X, const float* __restrict__ W,
    const float* __restrict__ B, float* __restrict__ OUT, int n)
{
    __shared__ float As[64][65];
    __shared__ __align__(16) float Ws[64][64];
    __shared__ float Bs[64];

    int t = threadIdx.x;
    int row0 = blockIdx.x * 64;
    int lane = t & 31, warp = t >> 5;

    #pragma unroll
    for (int i = 0; i < 4; i++)
        ((float4*)Ws)[t + i * 256] = ((const float4*)W)[t + i * 256];
    if (t < 64) Bs[t] = B[t];

    // gather: warp handles row pairs (rr, rr+1), 4 passes
    int half = lane >> 4;      // 0 or 1
    int q = lane & 15;         // float4 chunk
    const float4* X4 = (const float4*)X;
    #pragma unroll
    for (int pass = 0; pass < 4; pass++) {
        int r = warp * 2 + pass * 16 + half;
        float4 acc = gather_row(X4, row0 + r, q, n);
        As[r][q * 4 + 0] = acc.x;
        As[r][q * 4 + 1] = acc.y;
        As[r][q * 4 + 2] = acc.z;
        As[r][q * 4 + 3] = acc.w;
    }
    __syncthreads();

    // GEMM: 4x4 per thread
    int tx = t & 15, ty = t >> 4;
    float c[4][4];
    #pragma unroll
    for (int i = 0; i < 4; i++)
        #pragma unroll
        for (int jj = 0; jj < 4; jj++)
            c[i][jj] = Bs[tx * 4 + jj];

    #pragma unroll
    for (int k = 0; k < 64; k++) {
        float4 b = *(const float4*)&Ws[k][tx * 4];
        float a0 = As[ty * 4 + 0][k];
        float a1 = As[ty * 4 + 1][k];
        float a2 = As[ty * 4 + 2][k];
        float a3 = As[ty * 4 + 3][k];
        c[0][0] += a0 * b.x; c[0][1] += a0 * b.y; c[0][2] += a0 * b.z; c[0][3] += a0 * b.w;
        c[1][0] += a1 * b.x; c[1][1] += a1 * b.y; c[1][2] += a1 * b.z; c[1][3] += a1 * b.w;
        c[2][0] += a2 * b.x; c[2][1] += a2 * b.y; c[2][2] += a2 * b.z; c[2][3] += a2 * b.w;
        c[3][0] += a3 * b.x; c[3][1] += a3 * b.y; c[3][2] += a3 * b.z; c[3][3] += a3 * b.w;
    }

    #pragma unroll
    for (int i = 0; i < 4; i++) {
        int orow = row0 + ty * 4 + i;
        if (orow < n) {
            float4 o;
            o.x = fmaxf(c[i][0], 0.f);
            o.y = fmaxf(c[i][1], 0.f);
            o.z = fmaxf(c[i][2], 0.f);
            o.w = fmaxf(c[i][3], 0.f);
            ((float4*)OUT)[(long long)orow * 16 + tx] = o;
        }
    }
}

// ---------------- layer 2 + classifier + log_softmax, fully fused ----------------
// gather(h) -> (h+agg)@W2+b2,ReLU (h2 stays in smem) -> @Wf+bf -> log_softmax -> out
__global__ __launch_bounds__(256) void gin_layer2_final_kernel(
    const float* __restrict__ H, const float* __restrict__ W,
    const float* __restrict__ B, const float* __restrict__ WF,
    const float* __restrict__ BF, float* __restrict__ OUT, int n)
{
    __shared__ float As[64][65];
    __shared__ __align__(16) float Ws[64][64];
    __shared__ float Bs[64];
    __shared__ float Wf_s[64][40];
    __shared__ float Bf_s[40];

    int t = threadIdx.x;
    int row0 = blockIdx.x * 64;
    int lane = t & 31, warp = t >> 5;

    #pragma unroll
    for (int i = 0; i < 4; i++)
        ((float4*)Ws)[t + i * 256] = ((const float4*)W)[t + i * 256];
    if (t < 64) Bs[t] = B[t];
    for (int idx = t; idx < 64 * 40; idx += 256)
        Wf_s[idx / 40][idx % 40] = WF[idx];
    if (t < 40) Bf_s[t] = BF[t];

    // gather
    int half = lane >> 4;
    int q = lane & 15;
    const float4* H4 = (const float4*)H;
    #pragma unroll
    for (int pass = 0; pass < 4; pass++) {
        int r = warp * 2 + pass * 16 + half;
        float4 acc = gather_row(H4, row0 + r, q, n);
        As[r][q * 4 + 0] = acc.x;
        As[r][q * 4 + 1] = acc.y;
        As[r][q * 4 + 2] = acc.z;
        As[r][q * 4 + 3] = acc.w;
    }
    __syncthreads();

    // GEMM 1: h2 = relu((h+agg)@W2 + b2), kept in registers
    int tx = t & 15, ty = t >> 4;
    float c[4][4];
    #pragma unroll
    for (int i = 0; i < 4; i++)
        #pragma unroll
        for (int jj = 0; jj < 4; jj++)
            c[i][jj] = Bs[tx * 4 + jj];

    #pragma unroll
    for (int k = 0; k < 64; k++) {
        float4 b = *(const float4*)&Ws[k][tx * 4];
        float a0 = As[ty * 4 + 0][k];
        float a1 = As[ty * 4 + 1][k];
        float a2 = As[ty * 4 + 2][k];
        float a3 = As[ty * 4 + 3][k];
        c[0][0] += a0 * b.x; c[0][1] += a0 * b.y; c[0][2] += a0 * b.z; c[0][3] += a0 * b.w;
        c[1][0] += a1 * b.x; c[1][1] += a1 * b.y; c[1][2] += a1 * b.z; c[1][3] += a1 * b.w;
        c[2][0] += a2 * b.x; c[2][1] += a2 * b.y; c[2][2] += a2 * b.z; c[2][3] += a2 * b.w;
        c[3][0] += a3 * b.x; c[3][1] += a3 * b.y; c[3][2] += a3 * b.z; c[3][3] += a3 * b.w;
    }
    __syncthreads();   // everyone done reading As

    // restage relu(h2) into As
    #pragma unroll
    for (int i = 0; i < 4; i++) {
        int r = ty * 4 + i;
        As[r][tx * 4 + 0] = fmaxf(c[i][0], 0.f);
        As[r][tx * 4 + 1] = fmaxf(c[i][1], 0.f);
        As[r][tx * 4 + 2] = fmaxf(c[i][2], 0.f);
        As[r][tx * 4 + 3] = fmaxf(c[i][3], 0.f);
    }
    __syncthreads();

    // GEMM 2 + log_softmax: 4 threads/row, 10 cols each
    int tx4 = t & 3, ty4 = t >> 2;
    float acc[10];
    #pragma unroll
    for (int j = 0; j < 10; j++) acc[j] = Bf_s[tx4 * 10 + j];

    #pragma unroll
    for (int k = 0; k < 64; k++) {
        float a = As[ty4][k];
        #pragma unroll
        for (int j = 0; j < 10; j++)
            acc[j] += a * Wf_s[k][tx4 * 10 + j];
    }

    float m = acc[0];
    #pragma unroll
    for (int j = 1; j < 10; j++) m = fmaxf(m, acc[j]);
    m = fmaxf(m, __shfl_xor_sync(0xFFFFFFFFu, m, 1));
    m = fmaxf(m, __shfl_xor_sync(0xFFFFFFFFu, m, 2));

    float s = 0.f;
    #pragma unroll
    for (int j = 0; j < 10; j++) s += __expf(acc[j] - m);
    s += __shfl_xor_sync(0xFFFFFFFFu, s, 1);
    s += __shfl_xor_sync(0xFFFFFFFFu, s, 2);

    float ls = m + __logf(s);

    int row = row0 + ty4;
    if (row < n) {
        #pragma unroll
        for (int j = 0; j < 10; j++)
            OUT[(long long)row * NCLASS + tx4 * 10 + j] = acc[j] - ls;
    }
}

// ---------------- launch ----------------
extern "C" void kernel_launch(void* const* d_in, const int* in_sizes, int n_in,
                              void* d_out, int out_size) {
    const float* x  = (const float*)d_in[0];
    const void*  ei = d_in[1];
    const float* W1 = (const float*)d_in[2];
    const float* b1 = (const float*)d_in[3];
    const float* W2 = (const float*)d_in[4];
    const float* b2 = (const float*)d_in[5];
    const float* Wf = (const float*)d_in[6];
    const float* bf = (const float*)d_in[7];
    float* out = (float*)d_out;

    float* h; cudaGetSymbolAddress((void**)&h, g_h);

    const int n = N_NODES;
    const int EB = (N_EDGES + 255) / 256;
    const int NB = (N_NODES + 255) / 256;
    const int GB = (n + 63) / 64;

    // edge preprocessing + CSR build
    sniff_kernel<<<1, 256>>>((const unsigned int*)ei);
    zero_deg_kernel<<<NB, 256>>>();
    convert_hist_kernel<<<EB, 256>>>(ei);
    scan1_kernel<<<SCAN_NB, SCAN_B>>>();
    scan2_kernel<<<1, 128>>>();
    scan3_kernel<<<NB, 256>>>();
    fill_kernel<<<EB, 256>>>();

    // layer 1
    gin_layer1_kernel<<<GB, 256>>>(x, W1, b1, h, n);
    // layer 2 + classifier + log_softmax
    gin_layer2_final_kernel<<<GB, 256>>>(h, W2, b2, Wf, bf, out, n);
}